// round 16
// baseline (speedup 1.0000x reference)
#include <cuda_runtime.h>
#include <cuda_fp16.h>
#include <cstdint>

// Problem constants
#define NTOK   8192      // B*S
#define DIM    1024
#define NEXP   8
#define LN_EPS 1e-5f

// GEMM tiling (fp16 mma.sync m16n8k16 + ldmatrix)
#define MT 128
#define NT 128
#define KT 64            // halfs per k-stage -> 128B of k per row
#define NSTAGE 3
#define ASTR 72          // padded halfs per A row -> 144B stride (conflict-free LDSM)
#define BSTR 72
#define NBLK 296         // persistent CTAs (2 per SM)

#define SMEM_BYTES (NSTAGE*MT*ASTR*2 + NSTAGE*NT*BSTR*2 + MT*4 + MT*4)

// ---------------- scratch (device globals; no allocation allowed) -----------
__device__ int    d_cnt[NEXP];
__device__ int    d_tok[NEXP * NTOK];       // token index
__device__ float  d_wt [NEXP * NTOK];
__device__ __half d_xh [NTOK * DIM];        // x fp16 (emitted by routing)
__device__ __half d_wh [NEXP * DIM * DIM];  // W_exp transposed [e][n][k] fp16
__device__ int    d_items[NEXP * (NTOK / MT) * (DIM / NT)];
__device__ int    d_total;
__device__ int    d_work;

// ---------------- helpers ---------------------------------------------------
__device__ __forceinline__ void mma_f16(float c[4], const uint32_t a[4], const uint32_t b[2]) {
    asm volatile(
        "mma.sync.aligned.m16n8k16.row.col.f32.f16.f16.f32 "
        "{%0,%1,%2,%3}, {%4,%5,%6,%7}, {%8,%9}, {%0,%1,%2,%3};\n"
        : "+f"(c[0]), "+f"(c[1]), "+f"(c[2]), "+f"(c[3])
        : "r"(a[0]), "r"(a[1]), "r"(a[2]), "r"(a[3]),
          "r"(b[0]), "r"(b[1]));
}
__device__ __forceinline__ void ldsm_x4(uint32_t& r0, uint32_t& r1, uint32_t& r2, uint32_t& r3,
                                        uint32_t addr) {
    asm volatile("ldmatrix.sync.aligned.m8n8.x4.shared.b16 {%0,%1,%2,%3}, [%4];"
                 : "=r"(r0), "=r"(r1), "=r"(r2), "=r"(r3) : "r"(addr));
}
__device__ __forceinline__ void cp16(uint32_t dst, const void* src) {
    asm volatile("cp.async.cg.shared.global [%0], [%1], 16;" :: "r"(dst), "l"(src));
}
__device__ __forceinline__ void cp_commit() { asm volatile("cp.async.commit_group;"); }
__device__ __forceinline__ void cp_wait1()  { asm volatile("cp.async.wait_group 1;"); }
__device__ __forceinline__ void cp_wait0()  { asm volatile("cp.async.wait_group 0;"); }
__device__ __forceinline__ void red_v2(float* p, float v0, float v1) {
    asm volatile("red.global.add.v2.f32 [%0], {%1, %2};" :: "l"(p), "f"(v0), "f"(v1) : "memory");
}

// ---------------- kernel 0: zero output + counters ---------------------------
__global__ void zero_kernel(float* __restrict__ out) {
    size_t i = (size_t)blockIdx.x * blockDim.x + threadIdx.x;
    ((float4*)out)[i] = make_float4(0.f, 0.f, 0.f, 0.f);
    if (blockIdx.x == 0 && threadIdx.x < NEXP) d_cnt[threadIdx.x] = 0;
    if (blockIdx.x == 0 && threadIdx.x == NEXP) d_work = 0;
}

// ---------------- kernel: convert + transpose W_exp -> fp16 [e][n][k] --------
__global__ void convert_w(const float* __restrict__ W) {
    __shared__ __half t[32][33];
    int e  = blockIdx.z;
    int n0 = blockIdx.x * 32;
    int k0 = blockIdx.y * 32;
    int tx = threadIdx.x, ty = threadIdx.y;   // 32 x 8
    #pragma unroll
    for (int j = 0; j < 32; j += 8)
        t[ty + j][tx] = __float2half(W[((size_t)e * DIM + k0 + ty + j) * DIM + n0 + tx]);
    __syncthreads();
    #pragma unroll
    for (int j = 0; j < 32; j += 8)
        d_wh[((size_t)e * DIM + n0 + ty + j) * DIM + k0 + tx] = t[tx][ty + j];
}

// ---------------- kernel: routing (+ fp16 x emit) -----------------------------
__global__ __launch_bounds__(256) void routing_kernel(const float* __restrict__ x,
                                                      const float* __restrict__ noise,
                                                      const float* __restrict__ Wr,
                                                      const float* __restrict__ br,
                                                      const float* __restrict__ gamma,
                                                      const float* __restrict__ beta) {
    __shared__ float sW[8][1024];
    const int tid  = threadIdx.x;
    const int warp = tid >> 5;
    const int lane = tid & 31;

    const float4* w4 = (const float4*)Wr;
    for (int j = tid; j < 2048; j += 256) {
        float4 v = w4[j];
        int idx = j * 4;
        int d  = idx >> 3;
        int e0 = idx & 7;
        sW[e0 + 0][d] = v.x;
        sW[e0 + 1][d] = v.y;
        sW[e0 + 2][d] = v.z;
        sW[e0 + 3][d] = v.w;
    }
    __syncthreads();

    const int t = blockIdx.x * 8 + warp;
    const float4* xr = (const float4*)(x + (size_t)t * DIM);
    __half* xh = d_xh + (size_t)t * DIM;

    float acc[8] = {0.f,0.f,0.f,0.f,0.f,0.f,0.f,0.f};
    #pragma unroll
    for (int i = 0; i < 8; i++) {
        float4 xv = xr[i * 32 + lane];
        int d = i * 128 + lane * 4;
        #pragma unroll
        for (int e = 0; e < 8; e++) {
            float4 wv = *(const float4*)&sW[e][d];
            acc[e] += xv.x * wv.x + xv.y * wv.y + xv.z * wv.z + xv.w * wv.w;
        }
        __half2 h0 = __floats2half2_rn(xv.x, xv.y);
        __half2 h1 = __floats2half2_rn(xv.z, xv.w);
        *(__half2*)&xh[d + 0] = h0;
        *(__half2*)&xh[d + 2] = h1;
    }
    #pragma unroll
    for (int off = 16; off; off >>= 1) {
        #pragma unroll
        for (int e = 0; e < 8; e++)
            acc[e] += __shfl_down_sync(0xffffffffu, acc[e], off);
    }

    if (lane == 0) {
        float l[8];
        float mu = 0.f;
        #pragma unroll
        for (int e = 0; e < 8; e++) { l[e] = acc[e] + br[e]; mu += l[e]; }
        mu *= (1.f / 8.f);
        float var = 0.f;
        #pragma unroll
        for (int e = 0; e < 8; e++) { float d = l[e] - mu; var += d * d; }
        var *= (1.f / 8.f);
        float rstd = rsqrtf(var + LN_EPS);
        float mx = -1e30f;
        #pragma unroll
        for (int e = 0; e < 8; e++) {
            l[e] = (l[e] - mu) * rstd * gamma[e] + beta[e];
            mx = fmaxf(mx, l[e]);
        }
        float s = 0.f, p[8];
        #pragma unroll
        for (int e = 0; e < 8; e++) { p[e] = expf(l[e] - mx); s += p[e]; }
        float inv = 1.f / s;
        float r[8];
        #pragma unroll
        for (int e = 0; e < 8; e++) r[e] = p[e] * inv + noise[t * 8 + e];

        int i0 = 0; float v0 = r[0];
        #pragma unroll
        for (int e = 1; e < 8; e++) if (r[e] > v0) { v0 = r[e]; i0 = e; }
        int i1 = -1; float v1 = -1e30f;
        #pragma unroll
        for (int e = 0; e < 8; e++) if (e != i0 && r[e] > v1) { v1 = r[e]; i1 = e; }

        float e1 = expf(v1 - v0);
        float w0 = 1.f / (1.f + e1);
        float w1 = e1 / (1.f + e1);

        int p0 = atomicAdd(&d_cnt[i0], 1);
        d_tok[i0 * NTOK + p0] = t; d_wt[i0 * NTOK + p0] = w0;
        int p1 = atomicAdd(&d_cnt[i1], 1);
        d_tok[i1 * NTOK + p1] = t; d_wt[i1 * NTOK + p1] = w1;
    }
}

// ---------------- kernel: flatten tile work items -----------------------------
// encoding: item = (e << 12) | (m << 6) | nt   (e<8, m<64, nt<8)
__global__ void setup_kernel() {
    if (threadIdx.x == 0) {
        int n = 0;
        for (int e = 0; e < NEXP; e++) {
            int mt = (d_cnt[e] + MT - 1) / MT;
            for (int m = 0; m < mt; m++)
                for (int nt = 0; nt < DIM / NT; nt++)
                    d_items[n++] = (e << 12) | (m << 6) | nt;
        }
        d_total = n;
    }
}

// ---------------- kernel: persistent grouped expert GEMM ----------------------
// grid: NBLK blocks, 256 threads; work-stealing over (e, mtile, ntile) items
__global__ __launch_bounds__(256, 2) void moe_gemm(const float* __restrict__ bexp,
                                                   float* __restrict__ out) {
    extern __shared__ char smem_raw[];
    __half* As  = (__half*)smem_raw;                      // [NSTAGE][MT][ASTR]
    __half* Bs  = As + NSTAGE * MT * ASTR;                // [NSTAGE][NT][BSTR]
    int*   stok = (int*)(Bs + NSTAGE * NT * BSTR);        // [MT]
    float* swt  = (float*)(stok + MT);                    // [MT]
    __shared__ int s_item;

    const int tid  = threadIdx.x;
    const int warp = tid >> 5;
    const int lane = tid & 31;
    const int wm   = warp & 1;
    const int wn   = warp >> 1;
    const int gid  = lane >> 2;
    const int tg   = lane & 3;

    uint32_t as_base = (uint32_t)__cvta_generic_to_shared(As);
    uint32_t bs_base = (uint32_t)__cvta_generic_to_shared(Bs);

    const int a_r = (lane & 7) + ((lane >> 3) & 1) * 8;
    const int a_c = (lane >> 4) * 8;
    const int b_r = (lane & 7) + ((lane >> 4) << 3);
    const int b_c = ((lane >> 3) & 1) * 8;

    const int total = d_total;

    for (;;) {
        if (tid == 0) s_item = atomicAdd(&d_work, 1);
        __syncthreads();
        const int it = s_item;
        if (it >= total) break;

        const int item  = d_items[it];
        const int e     = item >> 12;
        const int mtile = (item >> 6) & 0x3F;
        const int ntile = item & 0x3F;
        const int cnt   = d_cnt[e];
        const int row0  = mtile * MT;
        const int n0    = ntile * NT;

        if (tid < MT) {
            int r = row0 + tid;
            bool ok = (r < cnt);
            stok[tid] = ok ? d_tok[e * NTOK + r] : -1;
            swt[tid]  = ok ? d_wt [e * NTOK + r] : 0.f;
        }
        __syncthreads();

        auto load_stage = [&](int s, int k0) {
            #pragma unroll
            for (int j = 0; j < 4; j++) {
                int idx = tid + 256 * j;
                int row = idx >> 3;
                int ch  = idx & 7;
                int tok = stok[row];
                uint32_t dst = as_base + (uint32_t)(((s * MT + row) * ASTR + ch * 8) * 2);
                if (tok >= 0) cp16(dst, d_xh + (size_t)tok * DIM + k0 + ch * 8);
                else asm volatile("st.shared.v4.b32 [%0], {%1,%1,%1,%1};" :: "r"(dst), "r"(0u));
            }
            #pragma unroll
            for (int j = 0; j < 4; j++) {
                int idx = tid + 256 * j;
                int row = idx >> 3;
                int ch  = idx & 7;
                uint32_t dst = bs_base + (uint32_t)(((s * NT + row) * BSTR + ch * 8) * 2);
                cp16(dst, d_wh + ((size_t)e * DIM + n0 + row) * DIM + k0 + ch * 8);
            }
        };

        float acc[4][4][4];
        #pragma unroll
        for (int mi = 0; mi < 4; mi++)
            #pragma unroll
            for (int ni = 0; ni < 4; ni++)
                #pragma unroll
                for (int q = 0; q < 4; q++) acc[mi][ni][q] = 0.f;

        load_stage(0, 0);      cp_commit();
        load_stage(1, KT);     cp_commit();

        const int NKT = DIM / KT;  // 16
        int cs = 0;
        for (int kt = 0; kt < NKT; kt++) {
            cp_wait1();
            __syncthreads();

            int ls = cs + 2; if (ls >= NSTAGE) ls -= NSTAGE;
            if (kt + 2 < NKT) load_stage(ls, (kt + 2) * KT);
            cp_commit();

            uint32_t asl = as_base + (uint32_t)(cs * MT * ASTR * 2);
            uint32_t bsl = bs_base + (uint32_t)(cs * NT * BSTR * 2);
            #pragma unroll
            for (int kk = 0; kk < KT; kk += 16) {
                uint32_t a[4][4], b[4][2];
                #pragma unroll
                for (int mi = 0; mi < 4; mi++) {
                    int rb = wm * 64 + mi * 16;
                    uint32_t addr = asl + (uint32_t)(((rb + a_r) * ASTR + kk + a_c) * 2);
                    ldsm_x4(a[mi][0], a[mi][1], a[mi][2], a[mi][3], addr);
                }
                #pragma unroll
                for (int p = 0; p < 2; p++) {
                    int cb = wn * 32 + p * 16;
                    uint32_t addr = bsl + (uint32_t)(((cb + b_r) * BSTR + kk + b_c) * 2);
                    ldsm_x4(b[p*2][0], b[p*2][1], b[p*2+1][0], b[p*2+1][1], addr);
                }
                #pragma unroll
                for (int mi = 0; mi < 4; mi++)
                    #pragma unroll
                    for (int ni = 0; ni < 4; ni++)
                        mma_f16(acc[mi][ni], a[mi], b[ni]);
            }

            cs++; if (cs >= NSTAGE) cs = 0;
        }
        cp_wait0();   // drain any stray groups before buffers are reused next item

        // epilogue: out[tok] += w * (acc + bias)
        #pragma unroll
        for (int mi = 0; mi < 4; mi++) {
            #pragma unroll
            for (int half = 0; half < 2; half++) {
                int r = wm * 64 + mi * 16 + half * 8 + gid;
                int tok = stok[r];
                if (tok < 0) continue;
                float w = swt[r];
                float* orow = out + (size_t)tok * DIM;
                #pragma unroll
                for (int ni = 0; ni < 4; ni++) {
                    int col = n0 + wn * 32 + ni * 8 + tg * 2;
                    float2 bb = *(const float2*)&bexp[e * DIM + col];
                    float v0 = w * (acc[mi][ni][half * 2 + 0] + bb.x);
                    float v1 = w * (acc[mi][ni][half * 2 + 1] + bb.y);
                    red_v2(&orow[col], v0, v1);
                }
            }
        }
        __syncthreads();   // stok/swt reuse safety for next item
    }
}

// ---------------- launch ------------------------------------------------------
extern "C" void kernel_launch(void* const* d_in, const int* in_sizes, int n_in,
                              void* d_out, int out_size) {
    const float* x     = (const float*)d_in[0];
    const float* noise = (const float*)d_in[1];
    const float* Wr    = (const float*)d_in[2];
    const float* br    = (const float*)d_in[3];
    const float* gamma = (const float*)d_in[4];
    const float* beta  = (const float*)d_in[5];
    const float* Wexp  = (const float*)d_in[6];
    const float* bexp  = (const float*)d_in[7];
    float* out = (float*)d_out;

    cudaFuncSetAttribute(moe_gemm, cudaFuncAttributeMaxDynamicSharedMemorySize, SMEM_BYTES);

    zero_kernel<<<(NTOK * DIM / 4) / 256, 256>>>(out);
    convert_w<<<dim3(DIM / 32, DIM / 32, NEXP), dim3(32, 8)>>>(Wexp);
    routing_kernel<<<NTOK / 8, 256>>>(x, noise, Wr, br, gamma, beta);
    setup_kernel<<<1, 32>>>();
    moe_gemm<<<NBLK, 256, SMEM_BYTES>>>(bexp, out);
}